// round 1
// baseline (speedup 1.0000x reference)
#include <cuda_runtime.h>
#include <cuda_bf16.h>
#include <cstdint>

// Problem constants
#define BATCH 2
#define HEADS 16
#define SEQ   2048
#define DMODEL 1024
#define DHEAD 64
#define OUT_ELEMS (BATCH * SEQ * DMODEL)  // 4,194,304

// ---------------- scratch (device globals: allocation-free) ----------------
__device__ float g_q[BATCH * HEADS * SEQ * DHEAD];   // [b,h,s,d]
__device__ float g_k[BATCH * HEADS * SEQ * DHEAD];
__device__ float g_v[BATCH * HEADS * SEQ * DHEAD];
__device__ float g_ctx[BATCH * SEQ * DMODEL];        // [b,s,D]

// ---------------- helpers ----------------
__device__ __forceinline__ uint32_t f2tf32(float x) {
    uint32_t r;
    asm("cvt.rna.tf32.f32 %0, %1;" : "=r"(r) : "f"(x));
    return r;
}

__device__ __forceinline__ void mma_tf32(float c[4],
                                         uint32_t a0, uint32_t a1, uint32_t a2, uint32_t a3,
                                         uint32_t b0, uint32_t b1) {
    asm volatile(
        "mma.sync.aligned.m16n8k8.row.col.f32.tf32.tf32.f32 "
        "{%0,%1,%2,%3}, {%4,%5,%6,%7}, {%8,%9}, {%0,%1,%2,%3};"
        : "+f"(c[0]), "+f"(c[1]), "+f"(c[2]), "+f"(c[3])
        : "r"(a0), "r"(a1), "r"(a2), "r"(a3), "r"(b0), "r"(b1));
}

// ---------------- GEMM: Y[M=4096, N=1024] = X @ W + bias ----------------
// mode 0/1/2: write head-split to g_q/g_k/g_v ; mode 3: X=g_ctx, write flat to Yext.
// CTA tile: 128(M) x 64(N), K-chunk 16. 8 warps (4x2), warp tile 32x32.
__global__ __launch_bounds__(256) void gemm_kernel(const float* __restrict__ Xext,
                                                   const float* __restrict__ W,
                                                   const float* __restrict__ bias,
                                                   float* __restrict__ Yext,
                                                   int mode) {
    __shared__ float As[16][132];   // [k][m], pad for conflict-free frag loads
    __shared__ float Bs[16][68];    // [k][n]

    const float* X = (mode == 3) ? g_ctx : Xext;

    const int m0 = blockIdx.y * 128;
    const int n0 = blockIdx.x * 64;
    const int tid = threadIdx.x;
    const int w = tid >> 5, lane = tid & 31;
    const int wm = w & 3, wn = w >> 2;          // warp rows wm*32, cols wn*32
    const int g = lane >> 2, tg = lane & 3;

    float acc[2][4][4];
#pragma unroll
    for (int mt = 0; mt < 2; mt++)
#pragma unroll
        for (int nt = 0; nt < 4; nt++)
#pragma unroll
            for (int i = 0; i < 4; i++) acc[mt][nt][i] = 0.f;

    for (int k0 = 0; k0 < DMODEL; k0 += 16) {
        // load A chunk 128x16 (transposed into As[k][m])
        {
            int r = tid >> 2;
            int c4 = (tid & 3) * 4;
#pragma unroll
            for (int p = 0; p < 2; p++) {
                int row = r + p * 64;
                float4 xv = *reinterpret_cast<const float4*>(&X[(size_t)(m0 + row) * DMODEL + k0 + c4]);
                As[c4 + 0][row] = xv.x;
                As[c4 + 1][row] = xv.y;
                As[c4 + 2][row] = xv.z;
                As[c4 + 3][row] = xv.w;
            }
            int br = tid >> 4;
            int bc = (tid & 15) * 4;
            float4 wv = *reinterpret_cast<const float4*>(&W[(size_t)(k0 + br) * DMODEL + n0 + bc]);
            *reinterpret_cast<float4*>(&Bs[br][bc]) = wv;
        }
        __syncthreads();

#pragma unroll
        for (int ks = 0; ks < 16; ks += 8) {
            uint32_t a[2][4];
#pragma unroll
            for (int mt = 0; mt < 2; mt++) {
                int rb = wm * 32 + mt * 16;
                a[mt][0] = f2tf32(As[ks + tg][rb + g]);
                a[mt][1] = f2tf32(As[ks + tg][rb + g + 8]);
                a[mt][2] = f2tf32(As[ks + tg + 4][rb + g]);
                a[mt][3] = f2tf32(As[ks + tg + 4][rb + g + 8]);
            }
            uint32_t b[4][2];
#pragma unroll
            for (int nt = 0; nt < 4; nt++) {
                int cb = wn * 32 + nt * 8 + g;
                b[nt][0] = f2tf32(Bs[ks + tg][cb]);
                b[nt][1] = f2tf32(Bs[ks + tg + 4][cb]);
            }
#pragma unroll
            for (int mt = 0; mt < 2; mt++)
#pragma unroll
                for (int nt = 0; nt < 4; nt++)
                    mma_tf32(acc[mt][nt], a[mt][0], a[mt][1], a[mt][2], a[mt][3],
                             b[nt][0], b[nt][1]);
        }
        __syncthreads();
    }

    // epilogue
    float* Yh = (mode == 0) ? g_q : (mode == 1) ? g_k : (mode == 2) ? g_v : Yext;
#pragma unroll
    for (int mt = 0; mt < 2; mt++) {
#pragma unroll
        for (int nt = 0; nt < 4; nt++) {
#pragma unroll
            for (int half = 0; half < 2; half++) {
                int m = m0 + wm * 32 + mt * 16 + g + half * 8;
                int n = n0 + wn * 32 + nt * 8 + tg * 2;
                float v0 = acc[mt][nt][half * 2 + 0] + bias[n];
                float v1 = acc[mt][nt][half * 2 + 1] + bias[n + 1];
                if (mode < 3) {
                    int b = m >> 11, s = m & 2047;
                    int h = n >> 6, d = n & 63;
                    size_t base = (((size_t)(b * HEADS + h) * SEQ + s) * DHEAD);
                    Yh[base + d] = v0;
                    Yh[base + d + 1] = v1;
                } else {
                    Yh[(size_t)m * DMODEL + n] = v0;
                    Yh[(size_t)m * DMODEL + n + 1] = v1;
                }
            }
        }
    }
}

// ---------------- attention ----------------
// grid: (SEQ/16, HEADS, BATCH), 256 threads (8 warps).
// Each CTA: 16 q rows vs all 2048 keys. Scores in SMEM (fp32), softmax,
// write attn_prob, then P@V with V chunks staged in SMEM, cross-warp reduce.
#define SC_STRIDE 2052
#define KS_STRIDE 68
#define VS_STRIDE 72
// smem floats: sc 16*2052 = 32832 ; kv 128*72 = 9216 ; Qs 16*68 = 1088
#define ATTN_SMEM_FLOATS (16 * SC_STRIDE + 128 * VS_STRIDE + 16 * 68)

__global__ __launch_bounds__(256, 1) void attn_kernel(float* __restrict__ attn_out) {
    extern __shared__ float smem[];
    float* sc = smem;                      // [16][SC_STRIDE]
    float* kv = smem + 16 * SC_STRIDE;     // K chunk (stride 68) / V chunk (stride 72) / reduce buf
    float* Qs = kv + 128 * VS_STRIDE;      // [16][68]

    const int tid = threadIdx.x;
    const int w = tid >> 5, lane = tid & 31;
    const int g = lane >> 2, tg = lane & 3;

    const int q0 = blockIdx.x * 16;
    const int h = blockIdx.y, b = blockIdx.z;
    const int bh = b * HEADS + h;

    const float* qh = g_q + (size_t)bh * SEQ * DHEAD;
    const float* kh = g_k + (size_t)bh * SEQ * DHEAD;
    const float* vh = g_v + (size_t)bh * SEQ * DHEAD;
    float* arow = attn_out + (size_t)bh * SEQ * SEQ + (size_t)q0 * SEQ;

    // load Q tile (16x64), fold 1/sqrt(dh) = 1/8 into Q
    for (int i = tid; i < 16 * DHEAD; i += 256) {
        int r = i >> 6, d = i & 63;
        Qs[r * 68 + d] = qh[(size_t)(q0 + r) * DHEAD + d] * 0.125f;
    }
    __syncthreads();

    // build Q A-fragments (whole 16x64 tile per warp: 8 k-steps x 4 regs)
    uint32_t qa[8][4];
#pragma unroll
    for (int s = 0; s < 8; s++) {
        qa[s][0] = f2tf32(Qs[g * 68 + s * 8 + tg]);
        qa[s][1] = f2tf32(Qs[(g + 8) * 68 + s * 8 + tg]);
        qa[s][2] = f2tf32(Qs[g * 68 + s * 8 + tg + 4]);
        qa[s][3] = f2tf32(Qs[(g + 8) * 68 + s * 8 + tg + 4]);
    }

    // ---- QK^T: scores [16][2048] in SMEM ----
    for (int c = 0; c < 16; c++) {
        const int kb = c * 128;
        // stage K chunk [128][64] into kv (stride 68)
        for (int i = tid; i < 128 * 16; i += 256) {
            int row = i >> 4;
            int c4 = (i & 15) * 4;
            float4 kvv = *reinterpret_cast<const float4*>(&kh[(size_t)(kb + row) * DHEAD + c4]);
            *reinterpret_cast<float4*>(&kv[row * KS_STRIDE + c4]) = kvv;
        }
        __syncthreads();

        float cacc[2][4];
#pragma unroll
        for (int nt = 0; nt < 2; nt++)
#pragma unroll
            for (int i = 0; i < 4; i++) cacc[nt][i] = 0.f;

#pragma unroll
        for (int s = 0; s < 8; s++) {
#pragma unroll
            for (int nt = 0; nt < 2; nt++) {
                int krow = w * 16 + nt * 8 + g;
                uint32_t b0 = f2tf32(kv[krow * KS_STRIDE + s * 8 + tg]);
                uint32_t b1 = f2tf32(kv[krow * KS_STRIDE + s * 8 + tg + 4]);
                mma_tf32(cacc[nt], qa[s][0], qa[s][1], qa[s][2], qa[s][3], b0, b1);
            }
        }
        // store scores
#pragma unroll
        for (int nt = 0; nt < 2; nt++) {
            int col = kb + w * 16 + nt * 8 + tg * 2;
            sc[g * SC_STRIDE + col] = cacc[nt][0];
            sc[g * SC_STRIDE + col + 1] = cacc[nt][1];
            sc[(g + 8) * SC_STRIDE + col] = cacc[nt][2];
            sc[(g + 8) * SC_STRIDE + col + 1] = cacc[nt][3];
        }
        __syncthreads();
    }

    // ---- softmax (2 rows per warp) + write attn_prob ----
    for (int rr = 0; rr < 2; rr++) {
        int r = w * 2 + rr;
        float* srow = sc + r * SC_STRIDE;
        float m = -1e30f;
        for (int ccc = lane; ccc < SEQ; ccc += 32) m = fmaxf(m, srow[ccc]);
#pragma unroll
        for (int o = 16; o > 0; o >>= 1) m = fmaxf(m, __shfl_xor_sync(0xffffffffu, m, o));
        float ssum = 0.f;
        for (int ccc = lane; ccc < SEQ; ccc += 32) {
            float e = __expf(srow[ccc] - m);
            srow[ccc] = e;
            ssum += e;
        }
#pragma unroll
        for (int o = 16; o > 0; o >>= 1) ssum += __shfl_xor_sync(0xffffffffu, ssum, o);
        float inv = 1.f / ssum;
        float* grow = arow + (size_t)r * SEQ;
        for (int ccc = lane * 4; ccc < SEQ; ccc += 128) {
            float4 e4 = *reinterpret_cast<float4*>(&srow[ccc]);
            e4.x *= inv; e4.y *= inv; e4.z *= inv; e4.w *= inv;
            *reinterpret_cast<float4*>(&srow[ccc]) = e4;
            *reinterpret_cast<float4*>(&grow[ccc]) = e4;
        }
    }
    __syncthreads();

    // ---- P @ V ----
    float oacc[8][4];
#pragma unroll
    for (int nt = 0; nt < 8; nt++)
#pragma unroll
        for (int i = 0; i < 4; i++) oacc[nt][i] = 0.f;

    for (int c = 0; c < 16; c++) {
        const int kb = c * 128;
        // stage V chunk [128][64] into kv (stride 72)
        for (int i = tid; i < 128 * 16; i += 256) {
            int row = i >> 4;
            int c4 = (i & 15) * 4;
            float4 vvv = *reinterpret_cast<const float4*>(&vh[(size_t)(kb + row) * DHEAD + c4]);
            *reinterpret_cast<float4*>(&kv[row * VS_STRIDE + c4]) = vvv;
        }
        __syncthreads();

        const int ks0 = w * 16;
#pragma unroll
        for (int s = 0; s < 2; s++) {
            const int kk = ks0 + s * 8;
            uint32_t a0 = f2tf32(sc[g * SC_STRIDE + kb + kk + tg]);
            uint32_t a1 = f2tf32(sc[(g + 8) * SC_STRIDE + kb + kk + tg]);
            uint32_t a2 = f2tf32(sc[g * SC_STRIDE + kb + kk + tg + 4]);
            uint32_t a3 = f2tf32(sc[(g + 8) * SC_STRIDE + kb + kk + tg + 4]);
#pragma unroll
            for (int nt = 0; nt < 8; nt++) {
                uint32_t b0 = f2tf32(kv[(kk + tg) * VS_STRIDE + nt * 8 + g]);
                uint32_t b1 = f2tf32(kv[(kk + tg + 4) * VS_STRIDE + nt * 8 + g]);
                mma_tf32(oacc[nt], a0, a1, a2, a3, b0, b1);
            }
        }
        __syncthreads();
    }

    // ---- cross-warp reduce ctx [16][64] and write ----
    float* red = kv;  // 8*1024 floats fits in 128*72
#pragma unroll
    for (int nt = 0; nt < 8; nt++) {
        int cb = nt * 8 + tg * 2;
        red[w * 1024 + g * 64 + cb] = oacc[nt][0];
        red[w * 1024 + g * 64 + cb + 1] = oacc[nt][1];
        red[w * 1024 + (g + 8) * 64 + cb] = oacc[nt][2];
        red[w * 1024 + (g + 8) * 64 + cb + 1] = oacc[nt][3];
    }
    __syncthreads();

    for (int i = tid; i < 1024; i += 256) {
        float sum = 0.f;
#pragma unroll
        for (int ww = 0; ww < 8; ww++) sum += red[ww * 1024 + i];
        int r = i >> 6, d = i & 63;
        g_ctx[((size_t)(b * SEQ + q0 + r)) * DMODEL + h * DHEAD + d] = sum;
    }
}

// ---------------- launch ----------------
extern "C" void kernel_launch(void* const* d_in, const int* in_sizes, int n_in,
                              void* d_out, int out_size) {
    const float* query = (const float*)d_in[0];
    const float* key   = (const float*)d_in[1];
    const float* value = (const float*)d_in[2];
    const float* Wq = (const float*)d_in[3];
    const float* bq = (const float*)d_in[4];
    const float* Wk = (const float*)d_in[5];
    const float* bk = (const float*)d_in[6];
    const float* Wv = (const float*)d_in[7];
    const float* bv = (const float*)d_in[8];
    const float* Wo = (const float*)d_in[9];
    const float* bo = (const float*)d_in[10];

    float* out = (float*)d_out;
    float* attn = out + OUT_ELEMS;

    static bool attr_set = false;
    if (!attr_set) {
        cudaFuncSetAttribute(attn_kernel, cudaFuncAttributeMaxDynamicSharedMemorySize,
                             ATTN_SMEM_FLOATS * sizeof(float));
        attr_set = true;
    }

    dim3 ggrid(DMODEL / 64, (BATCH * SEQ) / 128);
    gemm_kernel<<<ggrid, 256>>>(query, Wq, bq, nullptr, 0);
    gemm_kernel<<<ggrid, 256>>>(key,   Wk, bk, nullptr, 1);
    gemm_kernel<<<ggrid, 256>>>(value, Wv, bv, nullptr, 2);

    dim3 agrid(SEQ / 16, HEADS, BATCH);
    attn_kernel<<<agrid, 256, ATTN_SMEM_FLOATS * sizeof(float)>>>(attn);

    gemm_kernel<<<ggrid, 256>>>(nullptr, Wo, bo, out, 3);
}

// round 2
// speedup vs baseline: 1.5523x; 1.5523x over previous
#include <cuda_runtime.h>
#include <cuda_bf16.h>
#include <cstdint>

// Problem constants
#define BATCH 2
#define HEADS 16
#define SEQ   2048
#define DMODEL 1024
#define DHEAD 64
#define OUT_ELEMS (BATCH * SEQ * DMODEL)  // 4,194,304

// ---------------- scratch (device globals: allocation-free) ----------------
__device__ float g_q[BATCH * HEADS * SEQ * DHEAD];   // [b,h,s,d]
__device__ float g_k[BATCH * HEADS * SEQ * DHEAD];
__device__ float g_v[BATCH * HEADS * SEQ * DHEAD];
__device__ float g_ctx[BATCH * SEQ * DMODEL];        // [b,s,D]

// ---------------- helpers ----------------
__device__ __forceinline__ uint32_t f2tf32(float x) {
    uint32_t r;
    asm("cvt.rna.tf32.f32 %0, %1;" : "=r"(r) : "f"(x));
    return r;
}

__device__ __forceinline__ void mma_tf32(float c[4],
                                         uint32_t a0, uint32_t a1, uint32_t a2, uint32_t a3,
                                         uint32_t b0, uint32_t b1) {
    asm volatile(
        "mma.sync.aligned.m16n8k8.row.col.f32.tf32.tf32.f32 "
        "{%0,%1,%2,%3}, {%4,%5,%6,%7}, {%8,%9}, {%0,%1,%2,%3};"
        : "+f"(c[0]), "+f"(c[1]), "+f"(c[2]), "+f"(c[3])
        : "r"(a0), "r"(a1), "r"(a2), "r"(a3), "r"(b0), "r"(b1));
}

// ---------------- GEMM: Y[M=4096, N=1024] = X @ W + bias ----------------
// mode 0/1/2: write head-split to g_q/g_k/g_v ; mode 3: X=g_ctx, write flat to Yext.
__global__ __launch_bounds__(256) void gemm_kernel(const float* __restrict__ Xext,
                                                   const float* __restrict__ W,
                                                   const float* __restrict__ bias,
                                                   float* __restrict__ Yext,
                                                   int mode) {
    __shared__ float As[16][132];
    __shared__ float Bs[16][68];

    const float* X = (mode == 3) ? g_ctx : Xext;

    const int m0 = blockIdx.y * 128;
    const int n0 = blockIdx.x * 64;
    const int tid = threadIdx.x;
    const int w = tid >> 5, lane = tid & 31;
    const int wm = w & 3, wn = w >> 2;
    const int g = lane >> 2, tg = lane & 3;

    float acc[2][4][4];
#pragma unroll
    for (int mt = 0; mt < 2; mt++)
#pragma unroll
        for (int nt = 0; nt < 4; nt++)
#pragma unroll
            for (int i = 0; i < 4; i++) acc[mt][nt][i] = 0.f;

    for (int k0 = 0; k0 < DMODEL; k0 += 16) {
        {
            int r = tid >> 2;
            int c4 = (tid & 3) * 4;
#pragma unroll
            for (int p = 0; p < 2; p++) {
                int row = r + p * 64;
                float4 xv = *reinterpret_cast<const float4*>(&X[(size_t)(m0 + row) * DMODEL + k0 + c4]);
                As[c4 + 0][row] = xv.x;
                As[c4 + 1][row] = xv.y;
                As[c4 + 2][row] = xv.z;
                As[c4 + 3][row] = xv.w;
            }
            int br = tid >> 4;
            int bc = (tid & 15) * 4;
            float4 wv = *reinterpret_cast<const float4*>(&W[(size_t)(k0 + br) * DMODEL + n0 + bc]);
            *reinterpret_cast<float4*>(&Bs[br][bc]) = wv;
        }
        __syncthreads();

#pragma unroll
        for (int ks = 0; ks < 16; ks += 8) {
            uint32_t a[2][4];
#pragma unroll
            for (int mt = 0; mt < 2; mt++) {
                int rb = wm * 32 + mt * 16;
                a[mt][0] = f2tf32(As[ks + tg][rb + g]);
                a[mt][1] = f2tf32(As[ks + tg][rb + g + 8]);
                a[mt][2] = f2tf32(As[ks + tg + 4][rb + g]);
                a[mt][3] = f2tf32(As[ks + tg + 4][rb + g + 8]);
            }
            uint32_t b[4][2];
#pragma unroll
            for (int nt = 0; nt < 4; nt++) {
                int cb = wn * 32 + nt * 8 + g;
                b[nt][0] = f2tf32(Bs[ks + tg][cb]);
                b[nt][1] = f2tf32(Bs[ks + tg + 4][cb]);
            }
#pragma unroll
            for (int mt = 0; mt < 2; mt++)
#pragma unroll
                for (int nt = 0; nt < 4; nt++)
                    mma_tf32(acc[mt][nt], a[mt][0], a[mt][1], a[mt][2], a[mt][3],
                             b[nt][0], b[nt][1]);
        }
        __syncthreads();
    }

    float* Yh = (mode == 0) ? g_q : (mode == 1) ? g_k : (mode == 2) ? g_v : Yext;
#pragma unroll
    for (int mt = 0; mt < 2; mt++) {
#pragma unroll
        for (int nt = 0; nt < 4; nt++) {
#pragma unroll
            for (int half = 0; half < 2; half++) {
                int m = m0 + wm * 32 + mt * 16 + g + half * 8;
                int n = n0 + wn * 32 + nt * 8 + tg * 2;
                float v0 = acc[mt][nt][half * 2 + 0] + bias[n];
                float v1 = acc[mt][nt][half * 2 + 1] + bias[n + 1];
                if (mode < 3) {
                    int b = m >> 11, s = m & 2047;
                    int h = n >> 6, d = n & 63;
                    size_t base = (((size_t)(b * HEADS + h) * SEQ + s) * DHEAD);
                    Yh[base + d] = v0;
                    Yh[base + d + 1] = v1;
                } else {
                    Yh[(size_t)m * DMODEL + n] = v0;
                    Yh[(size_t)m * DMODEL + n + 1] = v1;
                }
            }
        }
    }
}

// ---------------- fused two-pass attention ----------------
// grid: (SEQ/64, HEADS, BATCH), 256 threads (8 warps, 4m x 2n).
// Pass A: stream K chunks, online (max,sum) per q row — exact softmax stats.
// Pass B: recompute S, P = exp(s-m)/l -> SMEM -> (coalesced attn write + P@V mma).
#define QT 64
#define CH 128
#define QS_STRIDE 68
#define KS_STRIDE 68
#define VS_STRIDE 68
#define PS_STRIDE 132
// smem floats: Qs 64*68=4352, Ks 128*68=8704 (>= 64*132=8448 for Ps), Vs 128*68=8704,
// mbuf 128, lbuf 128, sm_m 64, sm_inv 64
#define ATTN_SMEM_FLOATS (4352 + 8704 + 8704 + 128 + 128 + 64 + 64)

__global__ __launch_bounds__(256, 2) void attn_kernel(float* __restrict__ attn_out) {
    extern __shared__ float smem[];
    float* Qs   = smem;                 // [64][68]
    float* Ks   = Qs + 4352;            // [128][68]; reused as Ps [64][132]
    float* Vs   = Ks + 8704;            // [128][68]
    float* mbuf = Vs + 8704;            // [2][64]
    float* lbuf = mbuf + 128;           // [2][64]
    float* sm_m = lbuf + 128;           // [64]
    float* sm_i = sm_m + 64;            // [64]

    const int tid = threadIdx.x;
    const int w = tid >> 5, lane = tid & 31;
    const int wm = w & 3, wn = w >> 2;
    const int g = lane >> 2, tg = lane & 3;

    const int q0 = blockIdx.x * QT;
    const int h = blockIdx.y, b = blockIdx.z;
    const int bh = b * HEADS + h;

    const float* qh = g_q + (size_t)bh * SEQ * DHEAD;
    const float* kh = g_k + (size_t)bh * SEQ * DHEAD;
    const float* vh = g_v + (size_t)bh * SEQ * DHEAD;
    float* arow = attn_out + (size_t)bh * SEQ * SEQ + (size_t)q0 * SEQ;

    // ---- stage Q tile (64x64), fold 1/8 scale ----
    for (int i = tid; i < QT * 16; i += 256) {
        int r = i >> 4, c4 = (i & 15) * 4;
        float4 qv = *reinterpret_cast<const float4*>(&qh[(size_t)(q0 + r) * DHEAD + c4]);
        qv.x *= 0.125f; qv.y *= 0.125f; qv.z *= 0.125f; qv.w *= 0.125f;
        *reinterpret_cast<float4*>(&Qs[r * QS_STRIDE + c4]) = qv;
    }
    __syncthreads();

    // Q A-fragments for this warp's 16 rows (persist in regs)
    const int r0 = wm * 16 + g;
    uint32_t qa[8][4];
#pragma unroll
    for (int s = 0; s < 8; s++) {
        qa[s][0] = f2tf32(Qs[r0 * QS_STRIDE + s * 8 + tg]);
        qa[s][1] = f2tf32(Qs[(r0 + 8) * QS_STRIDE + s * 8 + tg]);
        qa[s][2] = f2tf32(Qs[r0 * QS_STRIDE + s * 8 + tg + 4]);
        qa[s][3] = f2tf32(Qs[(r0 + 8) * QS_STRIDE + s * 8 + tg + 4]);
    }

    // ================= PASS A: exact softmax stats =================
    float m0 = -1e30f, m1 = -1e30f, l0 = 0.f, l1 = 0.f;
    for (int c = 0; c < SEQ / CH; c++) {
        const int kb = c * CH;
        for (int i = tid; i < CH * 16; i += 256) {
            int r = i >> 4, c4 = (i & 15) * 4;
            *reinterpret_cast<float4*>(&Ks[r * KS_STRIDE + c4]) =
                *reinterpret_cast<const float4*>(&kh[(size_t)(kb + r) * DHEAD + c4]);
        }
        __syncthreads();

        float cacc[8][4];
#pragma unroll
        for (int nt = 0; nt < 8; nt++)
#pragma unroll
            for (int i = 0; i < 4; i++) cacc[nt][i] = 0.f;

#pragma unroll
        for (int s = 0; s < 8; s++) {
#pragma unroll
            for (int nt = 0; nt < 8; nt++) {
                int kr = wn * 64 + nt * 8 + g;
                uint32_t b0 = f2tf32(Ks[kr * KS_STRIDE + s * 8 + tg]);
                uint32_t b1 = f2tf32(Ks[kr * KS_STRIDE + s * 8 + tg + 4]);
                mma_tf32(cacc[nt], qa[s][0], qa[s][1], qa[s][2], qa[s][3], b0, b1);
            }
        }

        // chunk row max
        float cm0 = -1e30f, cm1 = -1e30f;
#pragma unroll
        for (int nt = 0; nt < 8; nt++) {
            cm0 = fmaxf(cm0, fmaxf(cacc[nt][0], cacc[nt][1]));
            cm1 = fmaxf(cm1, fmaxf(cacc[nt][2], cacc[nt][3]));
        }
#pragma unroll
        for (int o = 1; o < 4; o <<= 1) {
            cm0 = fmaxf(cm0, __shfl_xor_sync(0xffffffffu, cm0, o));
            cm1 = fmaxf(cm1, __shfl_xor_sync(0xffffffffu, cm1, o));
        }
        float nm0 = fmaxf(m0, cm0), nm1 = fmaxf(m1, cm1);
        float s0 = 0.f, s1 = 0.f;
#pragma unroll
        for (int nt = 0; nt < 8; nt++) {
            s0 += __expf(cacc[nt][0] - nm0) + __expf(cacc[nt][1] - nm0);
            s1 += __expf(cacc[nt][2] - nm1) + __expf(cacc[nt][3] - nm1);
        }
#pragma unroll
        for (int o = 1; o < 4; o <<= 1) {
            s0 += __shfl_xor_sync(0xffffffffu, s0, o);
            s1 += __shfl_xor_sync(0xffffffffu, s1, o);
        }
        l0 = l0 * __expf(m0 - nm0) + s0; m0 = nm0;
        l1 = l1 * __expf(m1 - nm1) + s1; m1 = nm1;
        __syncthreads();
    }

    // combine stats across the 2 n-warps
    if (tg == 0) {
        mbuf[wn * 64 + r0] = m0;     mbuf[wn * 64 + r0 + 8] = m1;
        lbuf[wn * 64 + r0] = l0;     lbuf[wn * 64 + r0 + 8] = l1;
    }
    __syncthreads();
    if (tid < 64) {
        float ma = mbuf[tid], mb2 = mbuf[64 + tid];
        float M = fmaxf(ma, mb2);
        float L = lbuf[tid] * __expf(ma - M) + lbuf[64 + tid] * __expf(mb2 - M);
        sm_m[tid] = M;
        sm_i[tid] = 1.f / L;
    }
    __syncthreads();
    const float M0 = sm_m[r0], M1 = sm_m[r0 + 8];
    const float I0 = sm_i[r0], I1 = sm_i[r0 + 8];

    // ================= PASS B: P write + P@V =================
    float* Ps = Ks;   // P chunk [64][132], aliases K buffer
    float oacc[4][4];
#pragma unroll
    for (int nt = 0; nt < 4; nt++)
#pragma unroll
        for (int i = 0; i < 4; i++) oacc[nt][i] = 0.f;

    for (int c = 0; c < SEQ / CH; c++) {
        const int kb = c * CH;
        for (int i = tid; i < CH * 16; i += 256) {
            int r = i >> 4, c4 = (i & 15) * 4;
            *reinterpret_cast<float4*>(&Ks[r * KS_STRIDE + c4]) =
                *reinterpret_cast<const float4*>(&kh[(size_t)(kb + r) * DHEAD + c4]);
            *reinterpret_cast<float4*>(&Vs[r * VS_STRIDE + c4]) =
                *reinterpret_cast<const float4*>(&vh[(size_t)(kb + r) * DHEAD + c4]);
        }
        __syncthreads();

        // recompute S chunk
        float cacc[8][4];
#pragma unroll
        for (int nt = 0; nt < 8; nt++)
#pragma unroll
            for (int i = 0; i < 4; i++) cacc[nt][i] = 0.f;
#pragma unroll
        for (int s = 0; s < 8; s++) {
#pragma unroll
            for (int nt = 0; nt < 8; nt++) {
                int kr = wn * 64 + nt * 8 + g;
                uint32_t b0 = f2tf32(Ks[kr * KS_STRIDE + s * 8 + tg]);
                uint32_t b1 = f2tf32(Ks[kr * KS_STRIDE + s * 8 + tg + 4]);
                mma_tf32(cacc[nt], qa[s][0], qa[s][1], qa[s][2], qa[s][3], b0, b1);
            }
        }
        __syncthreads();   // all warps done reading K before P overwrites it

        // P = exp(s - m) / l into Ps
#pragma unroll
        for (int nt = 0; nt < 8; nt++) {
            int col = wn * 64 + nt * 8 + tg * 2;
            float2 p0, p1;
            p0.x = __expf(cacc[nt][0] - M0) * I0;
            p0.y = __expf(cacc[nt][1] - M0) * I0;
            p1.x = __expf(cacc[nt][2] - M1) * I1;
            p1.y = __expf(cacc[nt][3] - M1) * I1;
            *reinterpret_cast<float2*>(&Ps[r0 * PS_STRIDE + col]) = p0;
            *reinterpret_cast<float2*>(&Ps[(r0 + 8) * PS_STRIDE + col]) = p1;
        }
        __syncthreads();

        // coalesced attn_prob write: 64 rows x 512B
        for (int i = tid; i < QT * 32; i += 256) {
            int r = i >> 5, c4 = (i & 31) * 4;
            *reinterpret_cast<float4*>(&arow[(size_t)r * SEQ + kb + c4]) =
                *reinterpret_cast<float4*>(&Ps[r * PS_STRIDE + c4]);
        }

        // O += P @ V  (each warp owns O rows wm*16..+16, cols wn*32..+32, full k)
#pragma unroll
        for (int ks = 0; ks < 16; ks++) {
            const int kk = ks * 8;
            uint32_t a0 = f2tf32(Ps[r0 * PS_STRIDE + kk + tg]);
            uint32_t a1 = f2tf32(Ps[(r0 + 8) * PS_STRIDE + kk + tg]);
            uint32_t a2 = f2tf32(Ps[r0 * PS_STRIDE + kk + tg + 4]);
            uint32_t a3 = f2tf32(Ps[(r0 + 8) * PS_STRIDE + kk + tg + 4]);
#pragma unroll
            for (int nt = 0; nt < 4; nt++) {
                int vcol = wn * 32 + nt * 8 + g;
                uint32_t b0 = f2tf32(Vs[(kk + tg) * VS_STRIDE + vcol]);
                uint32_t b1 = f2tf32(Vs[(kk + tg + 4) * VS_STRIDE + vcol]);
                mma_tf32(oacc[nt], a0, a1, a2, a3, b0, b1);
            }
        }
        __syncthreads();
    }

    // write context (head-interleaved layout for output projection)
#pragma unroll
    for (int nt = 0; nt < 4; nt++) {
        int cc = h * DHEAD + wn * 32 + nt * 8 + tg * 2;
        size_t base0 = ((size_t)(b * SEQ + q0 + r0)) * DMODEL + cc;
        size_t base1 = ((size_t)(b * SEQ + q0 + r0 + 8)) * DMODEL + cc;
        g_ctx[base0] = oacc[nt][0];
        g_ctx[base0 + 1] = oacc[nt][1];
        g_ctx[base1] = oacc[nt][2];
        g_ctx[base1 + 1] = oacc[nt][3];
    }
}

// ---------------- launch ----------------
extern "C" void kernel_launch(void* const* d_in, const int* in_sizes, int n_in,
                              void* d_out, int out_size) {
    const float* query = (const float*)d_in[0];
    const float* key   = (const float*)d_in[1];
    const float* value = (const float*)d_in[2];
    const float* Wq = (const float*)d_in[3];
    const float* bq = (const float*)d_in[4];
    const float* Wk = (const float*)d_in[5];
    const float* bk = (const float*)d_in[6];
    const float* Wv = (const float*)d_in[7];
    const float* bv = (const float*)d_in[8];
    const float* Wo = (const float*)d_in[9];
    const float* bo = (const float*)d_in[10];

    float* out = (float*)d_out;
    float* attn = out + OUT_ELEMS;

    static bool attr_set = false;
    if (!attr_set) {
        cudaFuncSetAttribute(attn_kernel, cudaFuncAttributeMaxDynamicSharedMemorySize,
                             ATTN_SMEM_FLOATS * sizeof(float));
        attr_set = true;
    }

    dim3 ggrid(DMODEL / 64, (BATCH * SEQ) / 128);
    gemm_kernel<<<ggrid, 256>>>(query, Wq, bq, nullptr, 0);
    gemm_kernel<<<ggrid, 256>>>(key,   Wk, bk, nullptr, 1);
    gemm_kernel<<<ggrid, 256>>>(value, Wv, bv, nullptr, 2);

    dim3 agrid(SEQ / QT, HEADS, BATCH);
    attn_kernel<<<agrid, 256, ATTN_SMEM_FLOATS * sizeof(float)>>>(attn);

    gemm_kernel<<<ggrid, 256>>>(nullptr, Wo, bo, out, 3);
}

// round 3
// speedup vs baseline: 1.6478x; 1.0615x over previous
#include <cuda_runtime.h>
#include <cuda_bf16.h>
#include <cstdint>

// Problem constants
#define BATCH 2
#define HEADS 16
#define SEQ   2048
#define DMODEL 1024
#define DHEAD 64
#define OUT_ELEMS (BATCH * SEQ * DMODEL)  // 4,194,304

// ---------------- scratch (device globals: allocation-free) ----------------
__device__ float g_q[BATCH * HEADS * SEQ * DHEAD];   // [b,h,s,d]
__device__ float g_k[BATCH * HEADS * SEQ * DHEAD];
__device__ float g_v[BATCH * HEADS * SEQ * DHEAD];
__device__ float g_ctx[BATCH * SEQ * DMODEL];        // [b,s,D]

// ---------------- helpers ----------------
__device__ __forceinline__ uint32_t f2tf32(float x) {
    uint32_t r;
    asm("cvt.rna.tf32.f32 %0, %1;" : "=r"(r) : "f"(x));
    return r;
}

__device__ __forceinline__ void mma_tf32(float c[4],
                                         uint32_t a0, uint32_t a1, uint32_t a2, uint32_t a3,
                                         uint32_t b0, uint32_t b1) {
    asm volatile(
        "mma.sync.aligned.m16n8k8.row.col.f32.tf32.tf32.f32 "
        "{%0,%1,%2,%3}, {%4,%5,%6,%7}, {%8,%9}, {%0,%1,%2,%3};"
        : "+f"(c[0]), "+f"(c[1]), "+f"(c[2]), "+f"(c[3])
        : "r"(a0), "r"(a1), "r"(a2), "r"(a3), "r"(b0), "r"(b1));
}

// ================= GEMM: Y[4096,1024] = X @ W + bias =================
// CTA 128x128, 8 warps as 2(m)x4(n), warp tile 64x32 (mt=4, nt=4).
// SMEM holds tf32-converted operands; reg double-buffer on global loads.
#define GAS 136
#define GBS 136

__global__ __launch_bounds__(256, 2) void gemm_kernel(const float* __restrict__ Xext,
                                                      const float* __restrict__ W,
                                                      const float* __restrict__ bias,
                                                      float* __restrict__ Yext,
                                                      int mode) {
    __shared__ uint32_t As[16 * GAS];   // [k][m] transposed, tf32
    __shared__ uint32_t Bs[16 * GBS];   // [k][n], tf32

    const float* X = (mode == 3) ? g_ctx : Xext;

    const int m0 = blockIdx.y * 128;
    const int n0 = blockIdx.x * 128;
    const int tid = threadIdx.x;
    const int w = tid >> 5, lane = tid & 31;
    const int wm = w & 1, wn = w >> 1;
    const int g = lane >> 2, tg = lane & 3;

    // staging assignment
    const int ar = tid & 127, akc = (tid >> 7) * 8;   // A: row ar, cols akc..akc+7
    const int br = tid >> 4, bc = (tid & 15) * 8;     // B: row br, cols bc..bc+7

    float acc[4][4][4];
#pragma unroll
    for (int mt = 0; mt < 4; mt++)
#pragma unroll
        for (int nt = 0; nt < 4; nt++)
#pragma unroll
            for (int i = 0; i < 4; i++) acc[mt][nt][i] = 0.f;

    // prologue global loads (chunk 0)
    float4 a0r = *reinterpret_cast<const float4*>(&X[(size_t)(m0 + ar) * DMODEL + akc]);
    float4 a1r = *reinterpret_cast<const float4*>(&X[(size_t)(m0 + ar) * DMODEL + akc + 4]);
    float4 b0r = *reinterpret_cast<const float4*>(&W[(size_t)br * DMODEL + n0 + bc]);
    float4 b1r = *reinterpret_cast<const float4*>(&W[(size_t)br * DMODEL + n0 + bc + 4]);

    for (int k0 = 0; k0 < DMODEL; k0 += 16) {
        // store staged chunk (tf32)
        As[(akc + 0) * GAS + ar] = f2tf32(a0r.x);
        As[(akc + 1) * GAS + ar] = f2tf32(a0r.y);
        As[(akc + 2) * GAS + ar] = f2tf32(a0r.z);
        As[(akc + 3) * GAS + ar] = f2tf32(a0r.w);
        As[(akc + 4) * GAS + ar] = f2tf32(a1r.x);
        As[(akc + 5) * GAS + ar] = f2tf32(a1r.y);
        As[(akc + 6) * GAS + ar] = f2tf32(a1r.z);
        As[(akc + 7) * GAS + ar] = f2tf32(a1r.w);
        {
            uint4 t0 = {f2tf32(b0r.x), f2tf32(b0r.y), f2tf32(b0r.z), f2tf32(b0r.w)};
            uint4 t1 = {f2tf32(b1r.x), f2tf32(b1r.y), f2tf32(b1r.z), f2tf32(b1r.w)};
            *reinterpret_cast<uint4*>(&Bs[br * GBS + bc]) = t0;
            *reinterpret_cast<uint4*>(&Bs[br * GBS + bc + 4]) = t1;
        }
        __syncthreads();

        // prefetch next chunk while computing
        if (k0 + 16 < DMODEL) {
            a0r = *reinterpret_cast<const float4*>(&X[(size_t)(m0 + ar) * DMODEL + k0 + 16 + akc]);
            a1r = *reinterpret_cast<const float4*>(&X[(size_t)(m0 + ar) * DMODEL + k0 + 16 + akc + 4]);
            b0r = *reinterpret_cast<const float4*>(&W[(size_t)(k0 + 16 + br) * DMODEL + n0 + bc]);
            b1r = *reinterpret_cast<const float4*>(&W[(size_t)(k0 + 16 + br) * DMODEL + n0 + bc + 4]);
        }

#pragma unroll
        for (int ks = 0; ks < 16; ks += 8) {
            uint32_t a[4][4], bf[4][2];
#pragma unroll
            for (int mt = 0; mt < 4; mt++) {
                int mm = wm * 64 + mt * 16 + g;
                a[mt][0] = As[(ks + tg) * GAS + mm];
                a[mt][1] = As[(ks + tg) * GAS + mm + 8];
                a[mt][2] = As[(ks + tg + 4) * GAS + mm];
                a[mt][3] = As[(ks + tg + 4) * GAS + mm + 8];
            }
#pragma unroll
            for (int nt = 0; nt < 4; nt++) {
                int nn = wn * 32 + nt * 8 + g;
                bf[nt][0] = Bs[(ks + tg) * GBS + nn];
                bf[nt][1] = Bs[(ks + tg + 4) * GBS + nn];
            }
#pragma unroll
            for (int mt = 0; mt < 4; mt++)
#pragma unroll
                for (int nt = 0; nt < 4; nt++)
                    mma_tf32(acc[mt][nt], a[mt][0], a[mt][1], a[mt][2], a[mt][3],
                             bf[nt][0], bf[nt][1]);
        }
        __syncthreads();
    }

    // epilogue
    float* Yh = (mode == 0) ? g_q : (mode == 1) ? g_k : (mode == 2) ? g_v : Yext;
#pragma unroll
    for (int nt = 0; nt < 4; nt++) {
        int n = n0 + wn * 32 + nt * 8 + tg * 2;
        float bi0 = __ldg(&bias[n]), bi1 = __ldg(&bias[n + 1]);
#pragma unroll
        for (int mt = 0; mt < 4; mt++) {
#pragma unroll
            for (int half = 0; half < 2; half++) {
                int m = m0 + wm * 64 + mt * 16 + g + half * 8;
                float v0 = acc[mt][nt][half * 2 + 0] + bi0;
                float v1 = acc[mt][nt][half * 2 + 1] + bi1;
                if (mode < 3) {
                    int b = m >> 11, s = m & 2047;
                    int h = n >> 6, d = n & 63;
                    size_t base = (((size_t)(b * HEADS + h) * SEQ + s) * DHEAD);
                    Yh[base + d] = v0;
                    Yh[base + d + 1] = v1;
                } else {
                    Yh[(size_t)m * DMODEL + n] = v0;
                    Yh[(size_t)m * DMODEL + n + 1] = v1;
                }
            }
        }
    }
}

// ================= fused two-pass attention =================
// grid (SEQ/64, HEADS, BATCH), 256 threads, warps 2(m)x4(n).
// SMEM operands stored as tf32 (uint32). attn_prob written from regs.
#define QT 64
#define CH 128
#define QSs 68
#define KSs 68
#define VSs 72
#define PSs 136
// u32 words: Qs 64*68=4352; Ks 128*68=8704 (== Ps 64*136); Vs 128*72=9216; stats 640
#define ATTN_SMEM_U32 (4352 + 8704 + 9216 + 640)

__global__ __launch_bounds__(256, 2) void attn_kernel(float* __restrict__ attn_out) {
    extern __shared__ uint32_t smem_u[];
    uint32_t* Qs = smem_u;
    uint32_t* Ks = Qs + 4352;            // aliased as Ps [64][136]
    uint32_t* Vs = Ks + 8704;
    float* mbuf = reinterpret_cast<float*>(Vs + 9216);   // [4][64]
    float* lbuf = mbuf + 256;                            // [4][64]
    float* smM = lbuf + 256;                             // [64]
    float* smI = smM + 64;                               // [64]

    const int tid = threadIdx.x;
    const int w = tid >> 5, lane = tid & 31;
    const int wm = w & 1, wn = w >> 1;
    const int g = lane >> 2, tg = lane & 3;

    const int q0 = blockIdx.x * QT;
    const int h = blockIdx.y, b = blockIdx.z;
    const int bh = b * HEADS + h;

    const float* qh = g_q + (size_t)bh * SEQ * DHEAD;
    const float* kh = g_k + (size_t)bh * SEQ * DHEAD;
    const float* vh = g_v + (size_t)bh * SEQ * DHEAD;
    float* arow = attn_out + (size_t)bh * SEQ * SEQ + (size_t)q0 * SEQ;

    // stage Q tile (tf32, fold 1/8)
    for (int i = tid; i < QT * 16; i += 256) {
        int r = i >> 4, c4 = (i & 15) * 4;
        float4 q4 = *reinterpret_cast<const float4*>(&qh[(size_t)(q0 + r) * DHEAD + c4]);
        uint4 t = {f2tf32(q4.x * 0.125f), f2tf32(q4.y * 0.125f),
                   f2tf32(q4.z * 0.125f), f2tf32(q4.w * 0.125f)};
        *reinterpret_cast<uint4*>(&Qs[r * QSs + c4]) = t;
    }
    __syncthreads();

    const int rA0 = wm * 32 + g;    // + mt*16, + 8 for the high half
    const int kc0 = wn * 32;        // this warp's 32-col slice of the 128-col chunk

    float mrun[4], lrun[4];
#pragma unroll
    for (int i = 0; i < 4; i++) { mrun[i] = -1e30f; lrun[i] = 0.f; }

    // ---------------- PASS A: exact softmax stats ----------------
    for (int c = 0; c < SEQ / CH; c++) {
        const int kb = c * CH;
        for (int i = tid; i < CH * 16; i += 256) {
            int r = i >> 4, c4 = (i & 15) * 4;
            float4 k4 = *reinterpret_cast<const float4*>(&kh[(size_t)(kb + r) * DHEAD + c4]);
            uint4 t = {f2tf32(k4.x), f2tf32(k4.y), f2tf32(k4.z), f2tf32(k4.w)};
            *reinterpret_cast<uint4*>(&Ks[r * KSs + c4]) = t;
        }
        __syncthreads();

        float sacc[2][4][4];
#pragma unroll
        for (int mt = 0; mt < 2; mt++)
#pragma unroll
            for (int nt = 0; nt < 4; nt++)
#pragma unroll
                for (int i = 0; i < 4; i++) sacc[mt][nt][i] = 0.f;

#pragma unroll
        for (int s = 0; s < 8; s++) {
            uint32_t a[2][4];
#pragma unroll
            for (int mt = 0; mt < 2; mt++) {
                int rr = rA0 + mt * 16;
                a[mt][0] = Qs[rr * QSs + s * 8 + tg];
                a[mt][1] = Qs[(rr + 8) * QSs + s * 8 + tg];
                a[mt][2] = Qs[rr * QSs + s * 8 + tg + 4];
                a[mt][3] = Qs[(rr + 8) * QSs + s * 8 + tg + 4];
            }
#pragma unroll
            for (int nt = 0; nt < 4; nt++) {
                int kr = kc0 + nt * 8 + g;
                uint32_t b0 = Ks[kr * KSs + s * 8 + tg];
                uint32_t b1 = Ks[kr * KSs + s * 8 + tg + 4];
                mma_tf32(sacc[0][nt], a[0][0], a[0][1], a[0][2], a[0][3], b0, b1);
                mma_tf32(sacc[1][nt], a[1][0], a[1][1], a[1][2], a[1][3], b0, b1);
            }
        }

#pragma unroll
        for (int mt = 0; mt < 2; mt++) {
            float cm0 = -1e30f, cm1 = -1e30f;
#pragma unroll
            for (int nt = 0; nt < 4; nt++) {
                cm0 = fmaxf(cm0, fmaxf(sacc[mt][nt][0], sacc[mt][nt][1]));
                cm1 = fmaxf(cm1, fmaxf(sacc[mt][nt][2], sacc[mt][nt][3]));
            }
#pragma unroll
            for (int o = 1; o < 4; o <<= 1) {
                cm0 = fmaxf(cm0, __shfl_xor_sync(0xffffffffu, cm0, o));
                cm1 = fmaxf(cm1, __shfl_xor_sync(0xffffffffu, cm1, o));
            }
            float nm0 = fmaxf(mrun[mt * 2], cm0);
            float nm1 = fmaxf(mrun[mt * 2 + 1], cm1);
            float s0 = 0.f, s1 = 0.f;
#pragma unroll
            for (int nt = 0; nt < 4; nt++) {
                s0 += __expf(sacc[mt][nt][0] - nm0) + __expf(sacc[mt][nt][1] - nm0);
                s1 += __expf(sacc[mt][nt][2] - nm1) + __expf(sacc[mt][nt][3] - nm1);
            }
#pragma unroll
            for (int o = 1; o < 4; o <<= 1) {
                s0 += __shfl_xor_sync(0xffffffffu, s0, o);
                s1 += __shfl_xor_sync(0xffffffffu, s1, o);
            }
            lrun[mt * 2]     = lrun[mt * 2]     * __expf(mrun[mt * 2]     - nm0) + s0;
            lrun[mt * 2 + 1] = lrun[mt * 2 + 1] * __expf(mrun[mt * 2 + 1] - nm1) + s1;
            mrun[mt * 2] = nm0;
            mrun[mt * 2 + 1] = nm1;
        }
        __syncthreads();
    }

    // combine stats across the 4 n-warps
    if (tg == 0) {
#pragma unroll
        for (int mt = 0; mt < 2; mt++) {
#pragma unroll
            for (int half = 0; half < 2; half++) {
                int row = rA0 + mt * 16 + half * 8;
                mbuf[wn * 64 + row] = mrun[mt * 2 + half];
                lbuf[wn * 64 + row] = lrun[mt * 2 + half];
            }
        }
    }
    __syncthreads();
    if (tid < 64) {
        float M = -1e30f;
#pragma unroll
        for (int j = 0; j < 4; j++) M = fmaxf(M, mbuf[j * 64 + tid]);
        float L = 0.f;
#pragma unroll
        for (int j = 0; j < 4; j++) L += lbuf[j * 64 + tid] * __expf(mbuf[j * 64 + tid] - M);
        smM[tid] = M;
        smI[tid] = 1.f / L;
    }
    __syncthreads();
    float Mx[4], Ix[4];
#pragma unroll
    for (int mt = 0; mt < 2; mt++)
#pragma unroll
        for (int half = 0; half < 2; half++) {
            Mx[mt * 2 + half] = smM[rA0 + mt * 16 + half * 8];
            Ix[mt * 2 + half] = smI[rA0 + mt * 16 + half * 8];
        }

    // ---------------- PASS B: P write + P@V ----------------
    uint32_t* Ps = Ks;
    const int vc0 = wn * 16;
    float oacc[2][2][4];
#pragma unroll
    for (int mt = 0; mt < 2; mt++)
#pragma unroll
        for (int nt = 0; nt < 2; nt++)
#pragma unroll
            for (int i = 0; i < 4; i++) oacc[mt][nt][i] = 0.f;

    for (int c = 0; c < SEQ / CH; c++) {
        const int kb = c * CH;
        for (int i = tid; i < CH * 16; i += 256) {
            int r = i >> 4, c4 = (i & 15) * 4;
            float4 k4 = *reinterpret_cast<const float4*>(&kh[(size_t)(kb + r) * DHEAD + c4]);
            uint4 tk = {f2tf32(k4.x), f2tf32(k4.y), f2tf32(k4.z), f2tf32(k4.w)};
            *reinterpret_cast<uint4*>(&Ks[r * KSs + c4]) = tk;
            float4 v4 = *reinterpret_cast<const float4*>(&vh[(size_t)(kb + r) * DHEAD + c4]);
            uint4 tv = {f2tf32(v4.x), f2tf32(v4.y), f2tf32(v4.z), f2tf32(v4.w)};
            *reinterpret_cast<uint4*>(&Vs[r * VSs + c4]) = tv;
        }
        __syncthreads();

        // S recompute
        float sacc[2][4][4];
#pragma unroll
        for (int mt = 0; mt < 2; mt++)
#pragma unroll
            for (int nt = 0; nt < 4; nt++)
#pragma unroll
                for (int i = 0; i < 4; i++) sacc[mt][nt][i] = 0.f;
#pragma unroll
        for (int s = 0; s < 8; s++) {
            uint32_t a[2][4];
#pragma unroll
            for (int mt = 0; mt < 2; mt++) {
                int rr = rA0 + mt * 16;
                a[mt][0] = Qs[rr * QSs + s * 8 + tg];
                a[mt][1] = Qs[(rr + 8) * QSs + s * 8 + tg];
                a[mt][2] = Qs[rr * QSs + s * 8 + tg + 4];
                a[mt][3] = Qs[(rr + 8) * QSs + s * 8 + tg + 4];
            }
#pragma unroll
            for (int nt = 0; nt < 4; nt++) {
                int kr = kc0 + nt * 8 + g;
                uint32_t b0 = Ks[kr * KSs + s * 8 + tg];
                uint32_t b1 = Ks[kr * KSs + s * 8 + tg + 4];
                mma_tf32(sacc[0][nt], a[0][0], a[0][1], a[0][2], a[0][3], b0, b1);
                mma_tf32(sacc[1][nt], a[1][0], a[1][1], a[1][2], a[1][3], b0, b1);
            }
        }
        __syncthreads();   // all warps done reading K before Ps overwrites it

        // P = exp(s-M)*I : write attn from regs, store tf32 to Ps
#pragma unroll
        for (int mt = 0; mt < 2; mt++) {
            int r0_ = rA0 + mt * 16, r1_ = r0_ + 8;
#pragma unroll
            for (int nt = 0; nt < 4; nt++) {
                int colL = kc0 + nt * 8 + tg * 2;
                float p0 = __expf(sacc[mt][nt][0] - Mx[mt * 2]) * Ix[mt * 2];
                float p1 = __expf(sacc[mt][nt][1] - Mx[mt * 2]) * Ix[mt * 2];
                float p2 = __expf(sacc[mt][nt][2] - Mx[mt * 2 + 1]) * Ix[mt * 2 + 1];
                float p3 = __expf(sacc[mt][nt][3] - Mx[mt * 2 + 1]) * Ix[mt * 2 + 1];
                float2 w0 = {p0, p1}, w1 = {p2, p3};
                *reinterpret_cast<float2*>(&arow[(size_t)r0_ * SEQ + kb + colL]) = w0;
                *reinterpret_cast<float2*>(&arow[(size_t)r1_ * SEQ + kb + colL]) = w1;
                uint2 u0 = {f2tf32(p0), f2tf32(p1)};
                uint2 u1 = {f2tf32(p2), f2tf32(p3)};
                *reinterpret_cast<uint2*>(&Ps[r0_ * PSs + colL]) = u0;
                *reinterpret_cast<uint2*>(&Ps[r1_ * PSs + colL]) = u1;
            }
        }
        __syncthreads();

        // O += P @ V
#pragma unroll
        for (int k = 0; k < 16; k++) {
            uint32_t pa[2][4];
#pragma unroll
            for (int mt = 0; mt < 2; mt++) {
                int rr = rA0 + mt * 16;
                pa[mt][0] = Ps[rr * PSs + k * 8 + tg];
                pa[mt][1] = Ps[(rr + 8) * PSs + k * 8 + tg];
                pa[mt][2] = Ps[rr * PSs + k * 8 + tg + 4];
                pa[mt][3] = Ps[(rr + 8) * PSs + k * 8 + tg + 4];
            }
#pragma unroll
            for (int nt = 0; nt < 2; nt++) {
                int vcol = vc0 + nt * 8 + g;
                uint32_t b0 = Vs[(k * 8 + tg) * VSs + vcol];
                uint32_t b1 = Vs[(k * 8 + tg + 4) * VSs + vcol];
                mma_tf32(oacc[0][nt], pa[0][0], pa[0][1], pa[0][2], pa[0][3], b0, b1);
                mma_tf32(oacc[1][nt], pa[1][0], pa[1][1], pa[1][2], pa[1][3], b0, b1);
            }
        }
        __syncthreads();
    }

    // write context (head-interleaved for output projection)
#pragma unroll
    for (int mt = 0; mt < 2; mt++) {
#pragma unroll
        for (int nt = 0; nt < 2; nt++) {
            int cc = h * DHEAD + vc0 + nt * 8 + tg * 2;
            int r0_ = rA0 + mt * 16, r1_ = r0_ + 8;
            float2 o0 = {oacc[mt][nt][0], oacc[mt][nt][1]};
            float2 o1 = {oacc[mt][nt][2], oacc[mt][nt][3]};
            *reinterpret_cast<float2*>(&g_ctx[((size_t)(b * SEQ + q0 + r0_)) * DMODEL + cc]) = o0;
            *reinterpret_cast<float2*>(&g_ctx[((size_t)(b * SEQ + q0 + r1_)) * DMODEL + cc]) = o1;
        }
    }
}

// ---------------- launch ----------------
extern "C" void kernel_launch(void* const* d_in, const int* in_sizes, int n_in,
                              void* d_out, int out_size) {
    const float* query = (const float*)d_in[0];
    const float* key   = (const float*)d_in[1];
    const float* value = (const float*)d_in[2];
    const float* Wq = (const float*)d_in[3];
    const float* bq = (const float*)d_in[4];
    const float* Wk = (const float*)d_in[5];
    const float* bk = (const float*)d_in[6];
    const float* Wv = (const float*)d_in[7];
    const float* bv = (const float*)d_in[8];
    const float* Wo = (const float*)d_in[9];
    const float* bo = (const float*)d_in[10];

    float* out = (float*)d_out;
    float* attn = out + OUT_ELEMS;

    static bool attr_set = false;
    if (!attr_set) {
        cudaFuncSetAttribute(attn_kernel, cudaFuncAttributeMaxDynamicSharedMemorySize,
                             ATTN_SMEM_U32 * 4);
        attr_set = true;
    }

    dim3 ggrid(DMODEL / 128, (BATCH * SEQ) / 128);
    gemm_kernel<<<ggrid, 256>>>(query, Wq, bq, nullptr, 0);
    gemm_kernel<<<ggrid, 256>>>(key,   Wk, bk, nullptr, 1);
    gemm_kernel<<<ggrid, 256>>>(value, Wv, bv, nullptr, 2);

    dim3 agrid(SEQ / QT, HEADS, BATCH);
    attn_kernel<<<agrid, 256, ATTN_SMEM_U32 * 4>>>(attn);

    gemm_kernel<<<ggrid, 256>>>(nullptr, Wo, bo, out, 3);
}

// round 5
// speedup vs baseline: 1.7432x; 1.0579x over previous
#include <cuda_runtime.h>
#include <cuda_bf16.h>
#include <cstdint>

// Problem constants
#define BATCH 2
#define HEADS 16
#define SEQ   2048
#define DMODEL 1024
#define DHEAD 64
#define OUT_ELEMS (BATCH * SEQ * DMODEL)  // 4,194,304

// ---------------- scratch (device globals: allocation-free) ----------------
__device__ float g_q[BATCH * HEADS * SEQ * DHEAD];   // [b,h,s,d]
__device__ float g_k[BATCH * HEADS * SEQ * DHEAD];
__device__ float g_v[BATCH * HEADS * SEQ * DHEAD];
__device__ float g_ctx[BATCH * SEQ * DMODEL];        // [b,s,D]

// ---------------- helpers ----------------
__device__ __forceinline__ uint32_t f2tf32(float x) {
    uint32_t r;
    asm("cvt.rna.tf32.f32 %0, %1;" : "=r"(r) : "f"(x));
    return r;
}

__device__ __forceinline__ void mma_tf32(float c[4],
                                         uint32_t a0, uint32_t a1, uint32_t a2, uint32_t a3,
                                         uint32_t b0, uint32_t b1) {
    asm volatile(
        "mma.sync.aligned.m16n8k8.row.col.f32.tf32.tf32.f32 "
        "{%0,%1,%2,%3}, {%4,%5,%6,%7}, {%8,%9}, {%0,%1,%2,%3};"
        : "+f"(c[0]), "+f"(c[1]), "+f"(c[2]), "+f"(c[3])
        : "r"(a0), "r"(a1), "r"(a2), "r"(a3), "r"(b0), "r"(b1));
}

// pack order within an 8-wide k-group: word positions hold cols [0,4,1,5,2,6,3,7]
// so cols (tg, tg+4) sit at adjacent words (2tg, 2tg+1)  ->  LDS.64 fragments.
// pk(c) = ((c&3)<<1) | (c>>2)
__device__ __forceinline__ void pack8(const float4& f0, const float4& f1,
                                      uint4& o0, uint4& o1) {
    o0.x = f2tf32(f0.x); o0.y = f2tf32(f1.x); o0.z = f2tf32(f0.y); o0.w = f2tf32(f1.y);
    o1.x = f2tf32(f0.z); o1.y = f2tf32(f1.z); o1.z = f2tf32(f0.w); o1.w = f2tf32(f1.w);
}

// ================= GEMM: Y[4096,1024] = X @ W + bias =================
// CTA 128x128, 8 warps 2(m)x4(n), warp tile 64x32 (mt=4, nt=4), k-chunk 16.
// A stored k-pair-packed per m-row; B stored [k][n].
#define GBS 136

__global__ __launch_bounds__(256, 2) void gemm_kernel(const float* __restrict__ Xext,
                                                      const float* __restrict__ W,
                                                      const float* __restrict__ bias,
                                                      float* __restrict__ Yext,
                                                      int mode) {
    __shared__ uint32_t As[2048];        // [g2][m][8 packed]  (2 groups x 128 m x 8)
    __shared__ uint32_t Bs[16 * GBS];    // [k][n]

    const float* X = (mode == 3) ? g_ctx : Xext;

    const int m0 = blockIdx.y * 128;
    const int n0 = blockIdx.x * 128;
    const int tid = threadIdx.x;
    const int w = tid >> 5, lane = tid & 31;
    const int wm = w & 1, wn = w >> 1;
    const int g = lane >> 2, tg = lane & 3;

    const int ar = tid & 127, ag2 = tid >> 7;         // A: row ar, k-group ag2
    const int br = tid >> 4, bc = (tid & 15) * 8;     // B: row br, cols bc..bc+7

    float acc[4][4][4];
#pragma unroll
    for (int mt = 0; mt < 4; mt++)
#pragma unroll
        for (int nt = 0; nt < 4; nt++)
#pragma unroll
            for (int i = 0; i < 4; i++) acc[mt][nt][i] = 0.f;

    float4 a0r = *reinterpret_cast<const float4*>(&X[(size_t)(m0 + ar) * DMODEL + ag2 * 8]);
    float4 a1r = *reinterpret_cast<const float4*>(&X[(size_t)(m0 + ar) * DMODEL + ag2 * 8 + 4]);
    float4 b0r = *reinterpret_cast<const float4*>(&W[(size_t)br * DMODEL + n0 + bc]);
    float4 b1r = *reinterpret_cast<const float4*>(&W[(size_t)br * DMODEL + n0 + bc + 4]);

    for (int k0 = 0; k0 < DMODEL; k0 += 16) {
        {
            uint4 p0, p1;
            pack8(a0r, a1r, p0, p1);
            *reinterpret_cast<uint4*>(&As[ag2 * 1024 + ar * 8]) = p0;
            *reinterpret_cast<uint4*>(&As[ag2 * 1024 + ar * 8 + 4]) = p1;
            uint4 t0 = {f2tf32(b0r.x), f2tf32(b0r.y), f2tf32(b0r.z), f2tf32(b0r.w)};
            uint4 t1 = {f2tf32(b1r.x), f2tf32(b1r.y), f2tf32(b1r.z), f2tf32(b1r.w)};
            *reinterpret_cast<uint4*>(&Bs[br * GBS + bc]) = t0;
            *reinterpret_cast<uint4*>(&Bs[br * GBS + bc + 4]) = t1;
        }
        __syncthreads();

        if (k0 + 16 < DMODEL) {
            a0r = *reinterpret_cast<const float4*>(&X[(size_t)(m0 + ar) * DMODEL + k0 + 16 + ag2 * 8]);
            a1r = *reinterpret_cast<const float4*>(&X[(size_t)(m0 + ar) * DMODEL + k0 + 16 + ag2 * 8 + 4]);
            b0r = *reinterpret_cast<const float4*>(&W[(size_t)(k0 + 16 + br) * DMODEL + n0 + bc]);
            b1r = *reinterpret_cast<const float4*>(&W[(size_t)(k0 + 16 + br) * DMODEL + n0 + bc + 4]);
        }

#pragma unroll
        for (int kg = 0; kg < 2; kg++) {           // two k=8 groups
            uint32_t a[4][4], bf[4][2];
#pragma unroll
            for (int mt = 0; mt < 4; mt++) {
                int mm = wm * 64 + mt * 16 + g;
                uint2 lo = *reinterpret_cast<uint2*>(&As[kg * 1024 + mm * 8 + 2 * tg]);
                uint2 hi = *reinterpret_cast<uint2*>(&As[kg * 1024 + (mm + 8) * 8 + 2 * tg]);
                a[mt][0] = lo.x; a[mt][1] = hi.x; a[mt][2] = lo.y; a[mt][3] = hi.y;
            }
#pragma unroll
            for (int nt = 0; nt < 4; nt++) {
                int nn = wn * 32 + nt * 8 + g;
                bf[nt][0] = Bs[(kg * 8 + tg) * GBS + nn];
                bf[nt][1] = Bs[(kg * 8 + tg + 4) * GBS + nn];
            }
#pragma unroll
            for (int mt = 0; mt < 4; mt++)
#pragma unroll
                for (int nt = 0; nt < 4; nt++)
                    mma_tf32(acc[mt][nt], a[mt][0], a[mt][1], a[mt][2], a[mt][3],
                             bf[nt][0], bf[nt][1]);
        }
        __syncthreads();
    }

    float* Yh = (mode == 0) ? g_q : (mode == 1) ? g_k : (mode == 2) ? g_v : Yext;
#pragma unroll
    for (int nt = 0; nt < 4; nt++) {
        int n = n0 + wn * 32 + nt * 8 + tg * 2;
        float bi0 = __ldg(&bias[n]), bi1 = __ldg(&bias[n + 1]);
#pragma unroll
        for (int mt = 0; mt < 4; mt++) {
#pragma unroll
            for (int half = 0; half < 2; half++) {
                int m = m0 + wm * 64 + mt * 16 + g + half * 8;
                float v0 = acc[mt][nt][half * 2 + 0] + bi0;
                float v1 = acc[mt][nt][half * 2 + 1] + bi1;
                if (mode < 3) {
                    int b = m >> 11, s = m & 2047;
                    int h = n >> 6, d = n & 63;
                    size_t base = (((size_t)(b * HEADS + h) * SEQ + s) * DHEAD);
                    Yh[base + d] = v0;
                    Yh[base + d + 1] = v1;
                } else {
                    Yh[(size_t)m * DMODEL + n] = v0;
                    Yh[(size_t)m * DMODEL + n + 1] = v1;
                }
            }
        }
    }
}

// ================= fused two-pass attention =================
// grid (SEQ/64, HEADS, BATCH), 256 threads, warps 2(m)x4(n).
// Q/K/P k-pair-packed (LDS.64 fragments), V plain.
#define QT 64
#define CH 128
#define QSs 72
#define KSs 72
#define VSs 72
#define PSs 136
// words: Qs 64*72=4608; Ks 128*72=9216 (aliased as Ps 64*136=8704); Vs 9216; stats 640
#define ATTN_SMEM_U32 (4608 + 9216 + 9216 + 640)

__global__ __launch_bounds__(256, 2) void attn_kernel(float* __restrict__ attn_out) {
    extern __shared__ uint32_t smem_u[];
    uint32_t* Qs = smem_u;
    uint32_t* Ks = Qs + 4608;
    uint32_t* Vs = Ks + 9216;
    float* mbuf = reinterpret_cast<float*>(Vs + 9216);   // [4][64]
    float* lbuf = mbuf + 256;                            // [4][64]
    float* smM = lbuf + 256;                             // [64]
    float* smI = smM + 64;                               // [64]

    const int tid = threadIdx.x;
    const int w = tid >> 5, lane = tid & 31;
    const int wm = w & 1, wn = w >> 1;
    const int g = lane >> 2, tg = lane & 3;

    const int q0 = blockIdx.x * QT;
    const int h = blockIdx.y, b = blockIdx.z;
    const int bh = b * HEADS + h;

    const float* qh = g_q + (size_t)bh * SEQ * DHEAD;
    const float* kh = g_k + (size_t)bh * SEQ * DHEAD;
    const float* vh = g_v + (size_t)bh * SEQ * DHEAD;
    float* arow = attn_out + (size_t)bh * SEQ * SEQ + (size_t)q0 * SEQ;

    // ---- stage Q (packed, fold 1/8) : 64 rows x 8 groups = 512 jobs ----
#pragma unroll
    for (int j = 0; j < 2; j++) {
        int id = j * 256 + tid;
        int r = id >> 3, grp = id & 7;
        float4 f0 = *reinterpret_cast<const float4*>(&qh[(size_t)(q0 + r) * DHEAD + grp * 8]);
        float4 f1 = *reinterpret_cast<const float4*>(&qh[(size_t)(q0 + r) * DHEAD + grp * 8 + 4]);
        f0.x *= 0.125f; f0.y *= 0.125f; f0.z *= 0.125f; f0.w *= 0.125f;
        f1.x *= 0.125f; f1.y *= 0.125f; f1.z *= 0.125f; f1.w *= 0.125f;
        uint4 p0, p1;
        pack8(f0, f1, p0, p1);
        *reinterpret_cast<uint4*>(&Qs[r * QSs + grp * 8]) = p0;
        *reinterpret_cast<uint4*>(&Qs[r * QSs + grp * 8 + 4]) = p1;
    }
    __syncthreads();

    const int rA0 = wm * 32 + g;    // + mt*16, + 8 for high half
    const int kc0 = wn * 32;        // this warp's 32-key slice

    float mrun[4], lrun[4];
#pragma unroll
    for (int i = 0; i < 4; i++) { mrun[i] = -1e30f; lrun[i] = 0.f; }

    // ---------------- PASS A: exact softmax stats ----------------
    for (int c = 0; c < SEQ / CH; c++) {
        const int kb = c * CH;
#pragma unroll
        for (int j = 0; j < 4; j++) {           // 128 rows x 8 groups / 256
            int id = j * 256 + tid;
            int r = id >> 3, grp = id & 7;
            float4 f0 = *reinterpret_cast<const float4*>(&kh[(size_t)(kb + r) * DHEAD + grp * 8]);
            float4 f1 = *reinterpret_cast<const float4*>(&kh[(size_t)(kb + r) * DHEAD + grp * 8 + 4]);
            uint4 p0, p1;
            pack8(f0, f1, p0, p1);
            *reinterpret_cast<uint4*>(&Ks[r * KSs + grp * 8]) = p0;
            *reinterpret_cast<uint4*>(&Ks[r * KSs + grp * 8 + 4]) = p1;
        }
        __syncthreads();

        float sacc[2][4][4];
#pragma unroll
        for (int mt = 0; mt < 2; mt++)
#pragma unroll
            for (int nt = 0; nt < 4; nt++)
#pragma unroll
                for (int i = 0; i < 4; i++) sacc[mt][nt][i] = 0.f;

#pragma unroll
        for (int s = 0; s < 8; s++) {
            uint32_t a[2][4];
#pragma unroll
            for (int mt = 0; mt < 2; mt++) {
                int rr = rA0 + mt * 16;
                uint2 lo = *reinterpret_cast<uint2*>(&Qs[rr * QSs + s * 8 + 2 * tg]);
                uint2 hi = *reinterpret_cast<uint2*>(&Qs[(rr + 8) * QSs + s * 8 + 2 * tg]);
                a[mt][0] = lo.x; a[mt][1] = hi.x; a[mt][2] = lo.y; a[mt][3] = hi.y;
            }
#pragma unroll
            for (int nt = 0; nt < 4; nt++) {
                int kr = kc0 + nt * 8 + g;
                uint2 bb = *reinterpret_cast<uint2*>(&Ks[kr * KSs + s * 8 + 2 * tg]);
                mma_tf32(sacc[0][nt], a[0][0], a[0][1], a[0][2], a[0][3], bb.x, bb.y);
                mma_tf32(sacc[1][nt], a[1][0], a[1][1], a[1][2], a[1][3], bb.x, bb.y);
            }
        }

#pragma unroll
        for (int mt = 0; mt < 2; mt++) {
            float cm0 = -1e30f, cm1 = -1e30f;
#pragma unroll
            for (int nt = 0; nt < 4; nt++) {
                cm0 = fmaxf(cm0, fmaxf(sacc[mt][nt][0], sacc[mt][nt][1]));
                cm1 = fmaxf(cm1, fmaxf(sacc[mt][nt][2], sacc[mt][nt][3]));
            }
#pragma unroll
            for (int o = 1; o < 4; o <<= 1) {
                cm0 = fmaxf(cm0, __shfl_xor_sync(0xffffffffu, cm0, o));
                cm1 = fmaxf(cm1, __shfl_xor_sync(0xffffffffu, cm1, o));
            }
            float nm0 = fmaxf(mrun[mt * 2], cm0);
            float nm1 = fmaxf(mrun[mt * 2 + 1], cm1);
            float s0 = 0.f, s1 = 0.f;
#pragma unroll
            for (int nt = 0; nt < 4; nt++) {
                s0 += __expf(sacc[mt][nt][0] - nm0) + __expf(sacc[mt][nt][1] - nm0);
                s1 += __expf(sacc[mt][nt][2] - nm1) + __expf(sacc[mt][nt][3] - nm1);
            }
#pragma unroll
            for (int o = 1; o < 4; o <<= 1) {
                s0 += __shfl_xor_sync(0xffffffffu, s0, o);
                s1 += __shfl_xor_sync(0xffffffffu, s1, o);
            }
            lrun[mt * 2]     = lrun[mt * 2]     * __expf(mrun[mt * 2]     - nm0) + s0;
            lrun[mt * 2 + 1] = lrun[mt * 2 + 1] * __expf(mrun[mt * 2 + 1] - nm1) + s1;
            mrun[mt * 2] = nm0;
            mrun[mt * 2 + 1] = nm1;
        }
        __syncthreads();
    }

    // combine stats across the 4 n-warps
    if (tg == 0) {
#pragma unroll
        for (int mt = 0; mt < 2; mt++) {
#pragma unroll
            for (int half = 0; half < 2; half++) {
                int row = rA0 + mt * 16 + half * 8;
                mbuf[wn * 64 + row] = mrun[mt * 2 + half];
                lbuf[wn * 64 + row] = lrun[mt * 2 + half];
            }
        }
    }
    __syncthreads();
    if (tid < 64) {
        float M = -1e30f;
#pragma unroll
        for (int j = 0; j < 4; j++) M = fmaxf(M, mbuf[j * 64 + tid]);
        float L = 0.f;
#pragma unroll
        for (int j = 0; j < 4; j++) L += lbuf[j * 64 + tid] * __expf(mbuf[j * 64 + tid] - M);
        smM[tid] = M;
        smI[tid] = 1.f / L;
    }
    __syncthreads();
    float Mx[4], Ix[4];
#pragma unroll
    for (int mt = 0; mt < 2; mt++)
#pragma unroll
        for (int half = 0; half < 2; half++) {
            Mx[mt * 2 + half] = smM[rA0 + mt * 16 + half * 8];
            Ix[mt * 2 + half] = smI[rA0 + mt * 16 + half * 8];
        }

    // ---------------- PASS B: P write + P@V ----------------
    uint32_t* Ps = Ks;                 // [64][136] packed, aliases K buffer
    const int vc0 = wn * 16;
    float oacc[2][2][4];
#pragma unroll
    for (int mt = 0; mt < 2; mt++)
#pragma unroll
        for (int nt = 0; nt < 2; nt++)
#pragma unroll
            for (int i = 0; i < 4; i++) oacc[mt][nt][i] = 0.f;

    for (int c = 0; c < SEQ / CH; c++) {
        const int kb = c * CH;
        // stage K (packed) + V (plain)
#pragma unroll
        for (int j = 0; j < 4; j++) {
            int id = j * 256 + tid;
            int r = id >> 3, grp = id & 7;
            float4 f0 = *reinterpret_cast<const float4*>(&kh[(size_t)(kb + r) * DHEAD + grp * 8]);
            float4 f1 = *reinterpret_cast<const float4*>(&kh[(size_t)(kb + r) * DHEAD + grp * 8 + 4]);
            uint4 p0, p1;
            pack8(f0, f1, p0, p1);
            *reinterpret_cast<uint4*>(&Ks[r * KSs + grp * 8]) = p0;
            *reinterpret_cast<uint4*>(&Ks[r * KSs + grp * 8 + 4]) = p1;
        }
#pragma unroll
        for (int j = 0; j < 8; j++) {
            int id = j * 256 + tid;
            int r = id >> 4, c4 = (id & 15) * 4;
            float4 v4 = *reinterpret_cast<const float4*>(&vh[(size_t)(kb + r) * DHEAD + c4]);
            uint4 tv = {f2tf32(v4.x), f2tf32(v4.y), f2tf32(v4.z), f2tf32(v4.w)};
            *reinterpret_cast<uint4*>(&Vs[r * VSs + c4]) = tv;
        }
        __syncthreads();

        // S recompute
        float sacc[2][4][4];
#pragma unroll
        for (int mt = 0; mt < 2; mt++)
#pragma unroll
            for (int nt = 0; nt < 4; nt++)
#pragma unroll
                for (int i = 0; i < 4; i++) sacc[mt][nt][i] = 0.f;
#pragma unroll
        for (int s = 0; s < 8; s++) {
            uint32_t a[2][4];
#pragma unroll
            for (int mt = 0; mt < 2; mt++) {
                int rr = rA0 + mt * 16;
                uint2 lo = *reinterpret_cast<uint2*>(&Qs[rr * QSs + s * 8 + 2 * tg]);
                uint2 hi = *reinterpret_cast<uint2*>(&Qs[(rr + 8) * QSs + s * 8 + 2 * tg]);
                a[mt][0] = lo.x; a[mt][1] = hi.x; a[mt][2] = lo.y; a[mt][3] = hi.y;
            }
#pragma unroll
            for (int nt = 0; nt < 4; nt++) {
                int kr = kc0 + nt * 8 + g;
                uint2 bb = *reinterpret_cast<uint2*>(&Ks[kr * KSs + s * 8 + 2 * tg]);
                mma_tf32(sacc[0][nt], a[0][0], a[0][1], a[0][2], a[0][3], bb.x, bb.y);
                mma_tf32(sacc[1][nt], a[1][0], a[1][1], a[1][2], a[1][3], bb.x, bb.y);
            }
        }
        __syncthreads();   // all warps done reading K before Ps overwrites it

        // P = exp(s-M)*I : gmem write from regs, packed tf32 into Ps
        // within a group, cols (2tg, 2tg+1) land at positions pk = ((c&3)<<1)|(c>>2)
        const int pk0 = ((2 * tg) & 3) * 2 + ((2 * tg) >> 2);
        const int pk1 = ((2 * tg + 1) & 3) * 2 + ((2 * tg + 1) >> 2);
#pragma unroll
        for (int mt = 0; mt < 2; mt++) {
            int r0_ = rA0 + mt * 16, r1_ = r0_ + 8;
#pragma unroll
            for (int nt = 0; nt < 4; nt++) {
                int gbase = kc0 + nt * 8;
                float p0 = __expf(sacc[mt][nt][0] - Mx[mt * 2]) * Ix[mt * 2];
                float p1 = __expf(sacc[mt][nt][1] - Mx[mt * 2]) * Ix[mt * 2];
                float p2 = __expf(sacc[mt][nt][2] - Mx[mt * 2 + 1]) * Ix[mt * 2 + 1];
                float p3 = __expf(sacc[mt][nt][3] - Mx[mt * 2 + 1]) * Ix[mt * 2 + 1];
                float2 w0 = {p0, p1}, w1 = {p2, p3};
                *reinterpret_cast<float2*>(&arow[(size_t)r0_ * SEQ + kb + gbase + 2 * tg]) = w0;
                *reinterpret_cast<float2*>(&arow[(size_t)r1_ * SEQ + kb + gbase + 2 * tg]) = w1;
                Ps[r0_ * PSs + gbase + pk0] = f2tf32(p0);
                Ps[r0_ * PSs + gbase + pk1] = f2tf32(p1);
                Ps[r1_ * PSs + gbase + pk0] = f2tf32(p2);
                Ps[r1_ * PSs + gbase + pk1] = f2tf32(p3);
            }
        }
        __syncthreads();

        // O += P @ V  (P A-frags via LDS.64)
#pragma unroll
        for (int kg = 0; kg < 16; kg++) {
            uint32_t pa[2][4];
#pragma unroll
            for (int mt = 0; mt < 2; mt++) {
                int rr = rA0 + mt * 16;
                uint2 lo = *reinterpret_cast<uint2*>(&Ps[rr * PSs + kg * 8 + 2 * tg]);
                uint2 hi = *reinterpret_cast<uint2*>(&Ps[(rr + 8) * PSs + kg * 8 + 2 * tg]);
                pa[mt][0] = lo.x; pa[mt][1] = hi.x; pa[mt][2] = lo.y; pa[mt][3] = hi.y;
            }
#pragma unroll
            for (int nt = 0; nt < 2; nt++) {
                int vcol = vc0 + nt * 8 + g;
                uint32_t b0 = Vs[(kg * 8 + tg) * VSs + vcol];
                uint32_t b1 = Vs[(kg * 8 + tg + 4) * VSs + vcol];
                mma_tf32(oacc[0][nt], pa[0][0], pa[0][1], pa[0][2], pa[0][3], b0, b1);
                mma_tf32(oacc[1][nt], pa[1][0], pa[1][1], pa[1][2], pa[1][3], b0, b1);
            }
        }
        __syncthreads();
    }

    // write context (head-interleaved for output projection)
#pragma unroll
    for (int mt = 0; mt < 2; mt++) {
#pragma unroll
        for (int nt = 0; nt < 2; nt++) {
            int cc = h * DHEAD + vc0 + nt * 8 + tg * 2;
            int r0_ = rA0 + mt * 16, r1_ = r0_ + 8;
            float2 o0 = {oacc[mt][nt][0], oacc[mt][nt][1]};
            float2 o1 = {oacc[mt][nt][2], oacc[mt][nt][3]};
            *reinterpret_cast<float2*>(&g_ctx[((size_t)(b * SEQ + q0 + r0_)) * DMODEL + cc]) = o0;
            *reinterpret_cast<float2*>(&g_ctx[((size_t)(b * SEQ + q0 + r1_)) * DMODEL + cc]) = o1;
        }
    }
}

// ---------------- launch ----------------
extern "C" void kernel_launch(void* const* d_in, const int* in_sizes, int n_in,
                              void* d_out, int out_size) {
    const float* query = (const float*)d_in[0];
    const float* key   = (const float*)d_in[1];
    const float* value = (const float*)d_in[2];
    const float* Wq = (const float*)d_in[3];
    const float* bq = (const float*)d_in[4];
    const float* Wk = (const float*)d_in[5];
    const float* bk = (const float*)d_in[6];
    const float* Wv = (const float*)d_in[7];
    const float* bv = (const float*)d_in[8];
    const float* Wo = (const float*)d_in[9];
    const float* bo = (const float*)d_in[10];

    float* out = (float*)d_out;
    float* attn = out + OUT_ELEMS;

    static bool attr_set = false;
    if (!attr_set) {
        cudaFuncSetAttribute(attn_kernel, cudaFuncAttributeMaxDynamicSharedMemorySize,
                             ATTN_SMEM_U32 * 4);
        attr_set = true;
    }

    dim3 ggrid(DMODEL / 128, (BATCH * SEQ) / 128);
    gemm_kernel<<<ggrid, 256>>>(query, Wq, bq, nullptr, 0);
    gemm_kernel<<<ggrid, 256>>>(key,   Wk, bk, nullptr, 1);
    gemm_kernel<<<ggrid, 256>>>(value, Wv, bv, nullptr, 2);

    dim3 agrid(SEQ / QT, HEADS, BATCH);
    attn_kernel<<<agrid, 256, ATTN_SMEM_U32 * 4>>>(attn);

    gemm_kernel<<<ggrid, 256>>>(nullptr, Wo, bo, out, 3);
}